// round 7
// baseline (speedup 1.0000x reference)
#include <cuda_runtime.h>
#include <cuda_fp16.h>
#include <cstdint>

// ============================================================================
// LPDecoder: out[e] = sigmoid( relu( [z[s]|z[d]] @ W1 + b1 ) @ W2 + b2 )
//
// UV = z @ [W1_top | W1_bot] + [b1 | 0]   (fp16 m16n8k16 MMA, fp32 accum)
// out[e] = sigmoid( relu(UV[s][0:128] + UV[d][128:256]) . W2 + b2 )
//
// R7: W1 transposed/swizzled/fp16-converted ONCE by a prep kernel into
//     g_W1t (64 KB, exact smem layout) -> gemm's B load is a conflict-free
//     uint4 copy. Both B halves smem-resident; by-loop has no reload/sync.
// ============================================================================

#define N_NODES_MAX 100000
#define SAP2 136            // sA row stride in halves (16B pad)

static __device__ __half g_UV[(size_t)N_NODES_MAX * 256];  // 51.2 MB scratch
static __device__ __half g_W1t[256 * 128];                 // 64 KB: [n_out][k], swizzled

// ----------------------------------------------------------------------------
// Prep: g_W1t[nout*128 + (k ^ ((nout&7)<<3))] = (half)W1[(nout>>7)*128 + k][nout&127]
// 32768 elements, one-time. Consecutive threads take consecutive k for a fixed
// nout -> global reads stride 512B (L2-cached, tiny), smem-free.
// ----------------------------------------------------------------------------
__global__ void __launch_bounds__(256)
prep_w1(const float* __restrict__ W1)
{
    int idx = blockIdx.x * blockDim.x + threadIdx.x;   // 32768 total
    if (idx >= 256 * 128) return;
    int nout = idx >> 7;          // 0..255
    int k    = idx & 127;         // 0..127
    int r    = ((nout >> 7) << 7) + k;    // W1 row
    int c    = nout & 127;                // W1 col
    float v  = W1[r * 128 + c];
    g_W1t[nout * 128 + (k ^ ((nout & 7) << 3))] = __float2half_rn(v);
}

// ----------------------------------------------------------------------------
// Kernel 1: UV[m][by*128+n] = sum_k z[m][k]*W1[by*128+k][n]  (+b1[n] for by=0)
// Block 256 thr (8 warps, 2x4), tile M=128 x N=256 (both halves), K=128.
// sA: [128][SAP2] halves. sB: [256 n][128 k] halves, XOR-swizzled, straight
// uint4 copy from g_W1t.
// ----------------------------------------------------------------------------
#define SMEM_HALVES (128 * SAP2 + 256 * 128)

__global__ void __launch_bounds__(256, 2)
gemm_uv(const float* __restrict__ z, const float* __restrict__ b1, int M)
{
    extern __shared__ __half smemh[];
    __half* sA = smemh;                 // [128][SAP2]
    __half* sB = smemh + 128 * SAP2;    // [256 n][128 k], swizzled

    const int tid = threadIdx.x;
    const int m0  = blockIdx.x * 128;

    // ---- Load A tile: z[m0..m0+127][0..127] -> fp16 sA ----
    #pragma unroll
    for (int it = 0; it < 16; ++it) {
        int idx = tid + it * 256;        // float4 index, 4096 total
        int r   = idx >> 5;
        int c4  = (idx & 31) << 2;
        float4 v = make_float4(0.f, 0.f, 0.f, 0.f);
        if (m0 + r < M)
            v = *(const float4*)(z + (size_t)(m0 + r) * 128 + c4);
        __half2* dst = (__half2*)(sA + r * SAP2 + c4);
        dst[0] = __floats2half2_rn(v.x, v.y);
        dst[1] = __floats2half2_rn(v.z, v.w);
    }
    // ---- Copy B (both halves): g_W1t -> sB, conflict-free uint4 ----
    {
        const uint4* src = (const uint4*)g_W1t;
        uint4*       dst = (uint4*)sB;
        #pragma unroll
        for (int it = 0; it < 16; ++it)
            dst[tid + it * 256] = src[tid + it * 256];
    }
    __syncthreads();

    const int w     = tid >> 5;
    const int lane  = tid & 31;
    const int g     = lane >> 2;   // groupID 0..7
    const int tig   = lane & 3;    // 0..3
    const int wr    = w >> 2;      // 0/1 -> rows wr*64 ..
    const int wc    = w & 3;       // cols wc*32 ..
    const int n0w   = wc * 32;
    const int rbase = wr * 64;

    #pragma unroll
    for (int by = 0; by < 2; ++by) {
        const __half* sBh = sB + by * 128 * 128;

        float c[4][4][4];
        #pragma unroll
        for (int mt = 0; mt < 4; ++mt)
            #pragma unroll
            for (int nt = 0; nt < 4; ++nt)
                #pragma unroll
                for (int i = 0; i < 4; ++i) c[mt][nt][i] = 0.f;

        #pragma unroll
        for (int kt = 0; kt < 8; ++kt) {
            const int ks = kt * 16 + 2 * tig;
            uint32_t bf[4][2];
            #pragma unroll
            for (int nt = 0; nt < 4; ++nt) {
                int n   = n0w + nt * 8 + g;       // n&7 == g
                int kx0 = ks ^ (g << 3);
                int kx1 = (ks + 8) ^ (g << 3);
                bf[nt][0] = *(const uint32_t*)(sBh + n * 128 + kx0);
                bf[nt][1] = *(const uint32_t*)(sBh + n * 128 + kx1);
            }
            #pragma unroll
            for (int mt = 0; mt < 4; ++mt) {
                int row = rbase + mt * 16 + g;
                uint32_t a0 = *(const uint32_t*)(sA + row * SAP2 + ks);
                uint32_t a1 = *(const uint32_t*)(sA + (row + 8) * SAP2 + ks);
                uint32_t a2 = *(const uint32_t*)(sA + row * SAP2 + ks + 8);
                uint32_t a3 = *(const uint32_t*)(sA + (row + 8) * SAP2 + ks + 8);
                #pragma unroll
                for (int nt = 0; nt < 4; ++nt) {
                    asm volatile(
                        "mma.sync.aligned.m16n8k16.row.col.f32.f16.f16.f32 "
                        "{%0,%1,%2,%3}, {%4,%5,%6,%7}, {%8,%9}, {%0,%1,%2,%3};"
                        : "+f"(c[mt][nt][0]), "+f"(c[mt][nt][1]),
                          "+f"(c[mt][nt][2]), "+f"(c[mt][nt][3])
                        : "r"(a0), "r"(a1), "r"(a2), "r"(a3),
                          "r"(bf[nt][0]), "r"(bf[nt][1]));
                }
            }
        }

        // ---- Epilogue: (+b1 if by==0), write fp16 UV ----
        #pragma unroll
        for (int mt = 0; mt < 4; ++mt) {
            int row0 = m0 + rbase + mt * 16 + g;
            int row1 = row0 + 8;
            #pragma unroll
            for (int nt = 0; nt < 4; ++nt) {
                int coln = n0w + nt * 8 + 2 * tig;
                float bx = 0.f, byv = 0.f;
                if (by == 0) {
                    float2 bb = *(const float2*)(b1 + coln);
                    bx = bb.x; byv = bb.y;
                }
                int colg = by * 128 + coln;
                if (row0 < M)
                    *(__half2*)(g_UV + (size_t)row0 * 256 + colg) =
                        __floats2half2_rn(c[mt][nt][0] + bx, c[mt][nt][1] + byv);
                if (row1 < M)
                    *(__half2*)(g_UV + (size_t)row1 * 256 + colg) =
                        __floats2half2_rn(c[mt][nt][2] + bx, c[mt][nt][3] + byv);
            }
        }
    }
}

// ----------------------------------------------------------------------------
// Kernel 2: half-warp per edge, 2 edges per half-warp per iteration.
// Lane covers 8 dims (uint4 = 8 halves). b1 already folded into UV.
//   h = relu(UV[s][j] + UV[d][128+j]);  out = sigmoid(h.W2 + b2)
// ----------------------------------------------------------------------------
__device__ __forceinline__ float edge_partial_h(int s, int d, int cb,
                                                float4 w2a, float4 w2b)
{
    uint4 ur = *(const uint4*)(g_UV + (size_t)s * 256 + cb);
    uint4 vr = *(const uint4*)(g_UV + (size_t)d * 256 + 128 + cb);
    const __half2 z2 = __half2half2(__ushort_as_half(0));

    __half2 h0 = __hmax2(__hadd2(*(__half2*)&ur.x, *(__half2*)&vr.x), z2);
    __half2 h1 = __hmax2(__hadd2(*(__half2*)&ur.y, *(__half2*)&vr.y), z2);
    __half2 h2 = __hmax2(__hadd2(*(__half2*)&ur.z, *(__half2*)&vr.z), z2);
    __half2 h3 = __hmax2(__hadd2(*(__half2*)&ur.w, *(__half2*)&vr.w), z2);

    float2 f0 = __half22float2(h0);
    float2 f1 = __half22float2(h1);
    float2 f2 = __half22float2(h2);
    float2 f3 = __half22float2(h3);

    return f0.x * w2a.x + f0.y * w2a.y + f1.x * w2a.z + f1.y * w2a.w
         + f2.x * w2b.x + f2.y * w2b.y + f3.x * w2b.z + f3.y * w2b.w;
}

__global__ void __launch_bounds__(256)
edge_kernel(const int* __restrict__ ei,
            const float* __restrict__ W2,
            const float* __restrict__ b2,
            float* __restrict__ out, int E)
{
    const int lane = threadIdx.x & 31;
    const int hw   = lane >> 4;          // half-warp id 0/1
    const int hl   = lane & 15;
    const int cb   = hl * 8;             // 8 halves per lane

    const int gwarp  = (blockIdx.x * blockDim.x + threadIdx.x) >> 5;
    const int nwarps = (gridDim.x * blockDim.x) >> 5;

    const float4 w2a = *(const float4*)(W2 + cb);
    const float4 w2b = *(const float4*)(W2 + cb + 4);
    const float bias2 = b2[0];

    for (int e0 = gwarp * 4; e0 < E; e0 += nwarps * 4) {
        int eA = e0 + hw;            // edges e0, e0+1 across the two halves
        int eB = e0 + 2 + hw;        // edges e0+2, e0+3
        bool vA = eA < E;
        bool vB = eB < E;

        int sA = vA ? ei[eA] : 0;
        int dA = vA ? ei[E + eA] : 0;
        int sB = vB ? ei[eB] : 0;
        int dB = vB ? ei[E + eB] : 0;

        float pA = edge_partial_h(sA, dA, cb, w2a, w2b);
        float pB = edge_partial_h(sB, dB, cb, w2a, w2b);

        #pragma unroll
        for (int off = 8; off > 0; off >>= 1) {
            pA += __shfl_xor_sync(0xffffffffu, pA, off);
            pB += __shfl_xor_sync(0xffffffffu, pB, off);
        }

        if (hl == 0) {
            if (vA) out[eA] = 1.0f / (1.0f + __expf(-(pA + bias2)));
            if (vB) out[eB] = 1.0f / (1.0f + __expf(-(pB + bias2)));
        }
    }
}

// ----------------------------------------------------------------------------
extern "C" void kernel_launch(void* const* d_in, const int* in_sizes, int n_in,
                              void* d_out, int out_size)
{
    const float* z   = (const float*)d_in[0];
    const int*   ei  = (const int*)d_in[1];
    const float* W1  = (const float*)d_in[2];
    const float* b1  = (const float*)d_in[3];
    const float* W2  = (const float*)d_in[4];
    const float* b2  = (const float*)d_in[5];
    float*       out = (float*)d_out;

    int M = in_sizes[0] / 128;   // nodes
    int E = in_sizes[1] / 2;     // edges

    const int smem_bytes = SMEM_HALVES * sizeof(__half);  // 100,352 B
    cudaFuncSetAttribute(gemm_uv, cudaFuncAttributeMaxDynamicSharedMemorySize,
                         smem_bytes);

    prep_w1<<<128, 256>>>(W1);
    gemm_uv<<<(M + 127) / 128, 256, smem_bytes>>>(z, b1, M);
    edge_kernel<<<1184, 256>>>(ei, W2, b2, out, E);
}

// round 8
// speedup vs baseline: 1.0311x; 1.0311x over previous
#include <cuda_runtime.h>
#include <cuda_fp16.h>
#include <cstdint>

// ============================================================================
// LPDecoder: out[e] = sigmoid( relu( [z[s]|z[d]] @ W1 + b1 ) @ W2 + b2 )
//
// UV = z @ [W1_top | W1_bot] + [b1 | 0]   (fp16 m16n8k16 MMA, fp32 accum)
// out[e] = sigmoid( relu(UV[s][0:128] + UV[d][128:256]) . W2 + b2 )
//
// R8: B operand read straight from L1-resident g_W1t (64 KB) -> no smem B,
//     no copy, one less sync. Edge dot in half2 (4 HFMA2 vs 8 CVT + 8 FFMA).
// ============================================================================

#define N_NODES_MAX 100000
#define SAP2 136            // sA row stride in halves (16B pad)

static __device__ __half g_UV[(size_t)N_NODES_MAX * 256];  // 51.2 MB scratch
static __device__ __half g_W1t[256 * 128];                 // 64 KB: [n_out][k]

// ----------------------------------------------------------------------------
// Prep: g_W1t[nout*128 + k] = (half) W1[ (nout>>7)*128 + k ][ nout&127 ]
// ----------------------------------------------------------------------------
__global__ void __launch_bounds__(256)
prep_w1(const float* __restrict__ W1)
{
    int idx = blockIdx.x * blockDim.x + threadIdx.x;   // 32768 total
    if (idx >= 256 * 128) return;
    int nout = idx >> 7;                  // 0..255
    int k    = idx & 127;                 // 0..127
    int r    = ((nout >> 7) << 7) + k;    // W1 row
    int c    = nout & 127;                // W1 col
    g_W1t[nout * 128 + k] = __float2half_rn(W1[r * 128 + c]);
}

// ----------------------------------------------------------------------------
// Kernel 1: UV[m][by*128+n] = sum_k z[m][k]*W1[by*128+k][n]  (+b1[n] for by=0)
// Block 256 thr (8 warps, 2x4), tile M=128 x N=256 (both halves), K=128.
// sA: [128][SAP2] halves. B fragments: LDG.32 from g_W1t (L1-resident).
// ----------------------------------------------------------------------------
#define SMEM_HALVES (128 * SAP2)

__global__ void __launch_bounds__(256, 2)
gemm_uv(const float* __restrict__ z, const float* __restrict__ b1, int M)
{
    extern __shared__ __half smemh[];
    __half* sA = smemh;                 // [128][SAP2]

    const int tid = threadIdx.x;
    const int m0  = blockIdx.x * 128;

    // ---- Load A tile: z[m0..m0+127][0..127] -> fp16 sA ----
    #pragma unroll
    for (int it = 0; it < 16; ++it) {
        int idx = tid + it * 256;        // float4 index, 4096 total
        int r   = idx >> 5;
        int c4  = (idx & 31) << 2;
        float4 v = make_float4(0.f, 0.f, 0.f, 0.f);
        if (m0 + r < M)
            v = *(const float4*)(z + (size_t)(m0 + r) * 128 + c4);
        __half2* dst = (__half2*)(sA + r * SAP2 + c4);
        dst[0] = __floats2half2_rn(v.x, v.y);
        dst[1] = __floats2half2_rn(v.z, v.w);
    }
    __syncthreads();

    const int w     = tid >> 5;
    const int lane  = tid & 31;
    const int g     = lane >> 2;   // groupID 0..7
    const int tig   = lane & 3;    // 0..3
    const int wr    = w >> 2;      // 0/1 -> rows wr*64 ..
    const int wc    = w & 3;       // cols wc*32 ..
    const int n0w   = wc * 32;
    const int rbase = wr * 64;

    #pragma unroll
    for (int by = 0; by < 2; ++by) {
        const __half* Bh = g_W1t + (size_t)by * 128 * 128;

        float c[4][4][4];
        #pragma unroll
        for (int mt = 0; mt < 4; ++mt)
            #pragma unroll
            for (int nt = 0; nt < 4; ++nt)
                #pragma unroll
                for (int i = 0; i < 4; ++i) c[mt][nt][i] = 0.f;

        #pragma unroll
        for (int kt = 0; kt < 8; ++kt) {
            const int ks = kt * 16 + 2 * tig;
            uint32_t bf[4][2];
            #pragma unroll
            for (int nt = 0; nt < 4; ++nt) {
                int n = n0w + nt * 8 + g;
                bf[nt][0] = *(const uint32_t*)(Bh + n * 128 + ks);
                bf[nt][1] = *(const uint32_t*)(Bh + n * 128 + ks + 8);
            }
            #pragma unroll
            for (int mt = 0; mt < 4; ++mt) {
                int row = rbase + mt * 16 + g;
                uint32_t a0 = *(const uint32_t*)(sA + row * SAP2 + ks);
                uint32_t a1 = *(const uint32_t*)(sA + (row + 8) * SAP2 + ks);
                uint32_t a2 = *(const uint32_t*)(sA + row * SAP2 + ks + 8);
                uint32_t a3 = *(const uint32_t*)(sA + (row + 8) * SAP2 + ks + 8);
                #pragma unroll
                for (int nt = 0; nt < 4; ++nt) {
                    asm volatile(
                        "mma.sync.aligned.m16n8k16.row.col.f32.f16.f16.f32 "
                        "{%0,%1,%2,%3}, {%4,%5,%6,%7}, {%8,%9}, {%0,%1,%2,%3};"
                        : "+f"(c[mt][nt][0]), "+f"(c[mt][nt][1]),
                          "+f"(c[mt][nt][2]), "+f"(c[mt][nt][3])
                        : "r"(a0), "r"(a1), "r"(a2), "r"(a3),
                          "r"(bf[nt][0]), "r"(bf[nt][1]));
                }
            }
        }

        // ---- Epilogue: (+b1 if by==0), write fp16 UV ----
        #pragma unroll
        for (int mt = 0; mt < 4; ++mt) {
            int row0 = m0 + rbase + mt * 16 + g;
            int row1 = row0 + 8;
            #pragma unroll
            for (int nt = 0; nt < 4; ++nt) {
                int coln = n0w + nt * 8 + 2 * tig;
                float bx = 0.f, byv = 0.f;
                if (by == 0) {
                    float2 bb = *(const float2*)(b1 + coln);
                    bx = bb.x; byv = bb.y;
                }
                int colg = by * 128 + coln;
                if (row0 < M)
                    *(__half2*)(g_UV + (size_t)row0 * 256 + colg) =
                        __floats2half2_rn(c[mt][nt][0] + bx, c[mt][nt][1] + byv);
                if (row1 < M)
                    *(__half2*)(g_UV + (size_t)row1 * 256 + colg) =
                        __floats2half2_rn(c[mt][nt][2] + bx, c[mt][nt][3] + byv);
            }
        }
    }
}

// ----------------------------------------------------------------------------
// Kernel 2: half-warp per edge, 2 edges per half-warp per iteration.
// Lane covers 8 dims (uint4 = 8 halves). b1 folded into UV. Dot in half2
// (fp16 products, 4-term fp16 chains, final pair summed in fp32).
// ----------------------------------------------------------------------------
__device__ __forceinline__ float edge_partial_h(int s, int d, int cb,
                                                __half2 w0, __half2 w1,
                                                __half2 w2h, __half2 w3)
{
    uint4 ur = *(const uint4*)(g_UV + (size_t)s * 256 + cb);
    uint4 vr = *(const uint4*)(g_UV + (size_t)d * 256 + 128 + cb);
    const __half2 z2 = __half2half2(__ushort_as_half(0));

    __half2 h0 = __hmax2(__hadd2(*(__half2*)&ur.x, *(__half2*)&vr.x), z2);
    __half2 h1 = __hmax2(__hadd2(*(__half2*)&ur.y, *(__half2*)&vr.y), z2);
    __half2 h2 = __hmax2(__hadd2(*(__half2*)&ur.z, *(__half2*)&vr.z), z2);
    __half2 h3 = __hmax2(__hadd2(*(__half2*)&ur.w, *(__half2*)&vr.w), z2);

    __half2 acc = __hmul2(h0, w0);
    acc = __hfma2(h1, w1, acc);
    acc = __hfma2(h2, w2h, acc);
    acc = __hfma2(h3, w3, acc);

    float2 f = __half22float2(acc);
    return f.x + f.y;
}

__global__ void __launch_bounds__(256)
edge_kernel(const int* __restrict__ ei,
            const float* __restrict__ W2,
            const float* __restrict__ b2,
            float* __restrict__ out, int E)
{
    const int lane = threadIdx.x & 31;
    const int hw   = lane >> 4;          // half-warp id 0/1
    const int hl   = lane & 15;
    const int cb   = hl * 8;             // 8 halves per lane

    const int gwarp  = (blockIdx.x * blockDim.x + threadIdx.x) >> 5;
    const int nwarps = (gridDim.x * blockDim.x) >> 5;

    const float4 w2a = *(const float4*)(W2 + cb);
    const float4 w2b = *(const float4*)(W2 + cb + 4);
    const __half2 w0 = __floats2half2_rn(w2a.x, w2a.y);
    const __half2 w1 = __floats2half2_rn(w2a.z, w2a.w);
    const __half2 w2h = __floats2half2_rn(w2b.x, w2b.y);
    const __half2 w3 = __floats2half2_rn(w2b.z, w2b.w);
    const float bias2 = b2[0];

    for (int e0 = gwarp * 4; e0 < E; e0 += nwarps * 4) {
        int eA = e0 + hw;            // edges e0, e0+1 across the two halves
        int eB = e0 + 2 + hw;        // edges e0+2, e0+3
        bool vA = eA < E;
        bool vB = eB < E;

        int sA = vA ? ei[eA] : 0;
        int dA = vA ? ei[E + eA] : 0;
        int sB = vB ? ei[eB] : 0;
        int dB = vB ? ei[E + eB] : 0;

        float pA = edge_partial_h(sA, dA, cb, w0, w1, w2h, w3);
        float pB = edge_partial_h(sB, dB, cb, w0, w1, w2h, w3);

        #pragma unroll
        for (int off = 8; off > 0; off >>= 1) {
            pA += __shfl_xor_sync(0xffffffffu, pA, off);
            pB += __shfl_xor_sync(0xffffffffu, pB, off);
        }

        if (hl == 0) {
            if (vA) out[eA] = 1.0f / (1.0f + __expf(-(pA + bias2)));
            if (vB) out[eB] = 1.0f / (1.0f + __expf(-(pB + bias2)));
        }
    }
}

// ----------------------------------------------------------------------------
extern "C" void kernel_launch(void* const* d_in, const int* in_sizes, int n_in,
                              void* d_out, int out_size)
{
    const float* z   = (const float*)d_in[0];
    const int*   ei  = (const int*)d_in[1];
    const float* W1  = (const float*)d_in[2];
    const float* b1  = (const float*)d_in[3];
    const float* W2  = (const float*)d_in[4];
    const float* b2  = (const float*)d_in[5];
    float*       out = (float*)d_out;

    int M = in_sizes[0] / 128;   // nodes
    int E = in_sizes[1] / 2;     // edges

    const int smem_bytes = SMEM_HALVES * sizeof(__half);  // 34,816 B
    cudaFuncSetAttribute(gemm_uv, cudaFuncAttributeMaxDynamicSharedMemorySize,
                         smem_bytes);

    prep_w1<<<128, 256>>>(W1);
    gemm_uv<<<(M + 127) / 128, 256, smem_bytes>>>(z, b1, M);
    edge_kernel<<<1184, 256>>>(ei, W2, b2, out, E);
}